// round 14
// baseline (speedup 1.0000x reference)
#include <cuda_runtime.h>
#include <math.h>

#define NN    1500
#define NE    48000
#define IND   128
#define OUTC  32
#define HEADS 4
#define HC    128
#define EDIM  16
#define CAP   128

#define NBLK  740            // 148 SMs * 5 blocks
#define NTHR  256
#define NWARP (NBLK * 8)     // 5920
#define SPLIT_DST 1460       // dsts [0,1460): 4 tasks (parity split); rest: 2 tasks
#define NTASK 5920           // 1460*4 + 40*2 == NWARP exactly

// ---- zeroed scratch (single small memset: 30KB) ---------------------------------
#define OFF_DEG   0          // 1500 ints (CSR degree)
#define OFF_EXS   1504       // 6000: per-(dst,head) sum of edge extras
#define OFF_BAR   7504       // 2 ints (count, sense)
#define ZTOTAL    7508
__device__ __align__(16) float g_z[ZTOTAL];

// ---- non-zeroed scratch (parity-private, written before read each run) ------------
__device__ int   g_ebuf[NN * CAP];                 // packed (eid<<11)|src
__device__ __align__(16) float g_ex[NE * HEADS];   // per-edge attn extras
__device__ __align__(16) float g_h[NN * HC];
__device__ __align__(16) float g_as[NN * HEADS];
__device__ __align__(16) float g_ad[NN * HEADS];
__device__ __align__(16) float g_h2[NN * HC];
__device__ __align__(16) float g_as2[NN * HEADS];
__device__ __align__(16) float g_ad2[NN * HEADS];
__device__ __align__(16) float g_agg1[NN * 2 * HC];   // [dst][par][h][c]
__device__ __align__(16) float g_agg2[NN * 2 * HC];
__device__ __align__(16) float g_s1[NN * 8];          // [dst][par][h]
__device__ __align__(16) float g_s2[NN * 8];
__device__ __align__(16) float g_y[NN * 64];          // y_top | y_bot per node

#define FILL_BASE  (NE * 2 / 4)          // 24000 float4
#define FILL_TOTAL (NN * NN * 2 / 4)     // 1125000 float4

// ---- grid barrier without CCTL.IVALL (R9/R12 proven; words zeroed by memset) ------
__device__ __forceinline__ void gbar(int phase) {
    __syncthreads();
    if (threadIdx.x == 0) {
        int* cnt = (int*)(g_z + OFF_BAR);
        int* sen = (int*)(g_z + OFF_BAR + 1);
        int prev;
        asm volatile("atom.acq_rel.gpu.add.s32 %0, [%1], 1;"
                     : "=r"(prev) : "l"(cnt) : "memory");
        if (prev == NBLK - 1) {
            *cnt = 0;
            asm volatile("st.release.gpu.s32 [%0], %1;"
                         :: "l"(sen), "r"(phase) : "memory");
        } else {
            int v;
            do {
                asm volatile("ld.acquire.gpu.s32 %0, [%1];"
                             : "=r"(v) : "l"(sen) : "memory");
            } while (v < phase);
        }
    }
    __syncthreads();
}

// ---- gather: exact task map; parity-private plain stores (no atomics) --------------
template <bool HAS_EXTRA>
__device__ __forceinline__ void gather_pass(const float* __restrict__ hb,
                                            const float* __restrict__ asb,
                                            const float* __restrict__ adb,
                                            float* __restrict__ agg,
                                            float* __restrict__ sbuf,
                                            int task, int lane) {
    int dst, hp, par, step;
    if (task < SPLIT_DST * 4) {
        dst = task >> 2; hp = (task >> 1) & 1; par = task & 1; step = 2;
    } else {
        int u = task - SPLIT_DST * 4;
        dst = SPLIT_DST + (u >> 1); hp = u & 1; par = 0; step = 1;
    }
    int h   = (hp << 1) + (lane >> 4);
    int l16 = lane & 15;
    int deg = ((const int*)(g_z + OFF_DEG))[dst];
    float ad_d = adb[dst * HEADS + h];
    const int* eb = g_ebuf + dst * CAP;

    float s = 0.f, ax = 0.f, ay = 0.f;
    int k = par;
    #pragma unroll 1
    for (; k + 3 * step < deg; k += 4 * step) {
        int p[4]; float ex[4], asv[4]; float2 hv[4];
        #pragma unroll
        for (int u = 0; u < 4; u++) p[u] = eb[k + u * step];
        #pragma unroll
        for (int u = 0; u < 4; u++) {
            int src = p[u] & 2047;
            ex[u]  = HAS_EXTRA ? g_ex[(p[u] >> 11) * HEADS + h] : 0.f;
            asv[u] = asb[src * HEADS + h];
            hv[u]  = *reinterpret_cast<const float2*>(hb + src * HC + h * OUTC + l16 * 2);
        }
        #pragma unroll
        for (int u = 0; u < 4; u++) {
            float a = asv[u] + ad_d + ex[u];
            a = (a > 0.f) ? a : 0.2f * a;
            float e = __expf(a);
            s += e;
            ax = fmaf(e, hv[u].x, ax);
            ay = fmaf(e, hv[u].y, ay);
        }
    }
    for (; k < deg; k += step) {
        int p = eb[k];
        int src = p & 2047;
        float ex = HAS_EXTRA ? g_ex[(p >> 11) * HEADS + h] : 0.f;
        float a = asb[src * HEADS + h] + ad_d + ex;
        a = (a > 0.f) ? a : 0.2f * a;
        float e = __expf(a);
        s += e;
        float2 hv = *reinterpret_cast<const float2*>(hb + src * HC + h * OUTC + l16 * 2);
        ax = fmaf(e, hv.x, ax);
        ay = fmaf(e, hv.y, ay);
    }
    if (par == 0) {   // self loop: attr = mean of incoming extras (0 if deg==0)
        float ex_sl = HAS_EXTRA
            ? __fdividef(g_z[OFF_EXS + dst * HEADS + h], fmaxf((float)deg, 1.f)) : 0.f;
        float a = asb[dst * HEADS + h] + ad_d + ex_sl;
        a = (a > 0.f) ? a : 0.2f * a;
        float e = __expf(a);
        s += e;
        float2 hv = *reinterpret_cast<const float2*>(hb + dst * HC + h * OUTC + l16 * 2);
        ax = fmaf(e, hv.x, ax);
        ay = fmaf(e, hv.y, ay);
    }
    // private slot: plain stores, no RMW
    *reinterpret_cast<float2*>(agg + dst * (2 * HC) + par * HC + h * OUTC + l16 * 2)
        = make_float2(ax, ay);
    if (l16 == 0) sbuf[dst * 8 + par * 4 + h] = s;
}

// combine parity halves + normalize + mean heads (+bias)
__device__ __forceinline__ float xval(const float* __restrict__ agg,
                                      const float* __restrict__ sbuf,
                                      int row, int c, float bias) {
    const float* ag = agg + row * (2 * HC);
    float4 s0 = *reinterpret_cast<const float4*>(sbuf + row * 8);
    float acc;
    if (row < SPLIT_DST) {
        float4 s1 = *reinterpret_cast<const float4*>(sbuf + row * 8 + 4);
        acc = __fdividef(ag[c]            + ag[HC + c],            s0.x + s1.x)
            + __fdividef(ag[OUTC + c]     + ag[HC + OUTC + c],     s0.y + s1.y)
            + __fdividef(ag[2 * OUTC + c] + ag[HC + 2 * OUTC + c], s0.z + s1.z)
            + __fdividef(ag[3 * OUTC + c] + ag[HC + 3 * OUTC + c], s0.w + s1.w);
    } else {
        acc = __fdividef(ag[c],            s0.x)
            + __fdividef(ag[OUTC + c],     s0.y)
            + __fdividef(ag[2 * OUTC + c], s0.z)
            + __fdividef(ag[3 * OUTC + c], s0.w);
    }
    return 0.25f * acc + bias;
}

// smem: [0..511] proj1 staging / weatt; [512..2559] fc1_w; [2560..2591] fc1_b;
//       [2592..2655] fc2_w; [2656..2657] fc2_b
#define SH_W1 512
#define SH_B1 2560
#define SH_W2 2592
#define SH_B2 2656

// ================= the single persistent kernel ======================================
__global__ void __launch_bounds__(NTHR, 5) k_fused(
    const int* __restrict__ edges, const float* __restrict__ ef,
    const float* __restrict__ x, const float* __restrict__ W1,
    const float* __restrict__ as1, const float* __restrict__ ad1,
    const float* __restrict__ We, const float* __restrict__ att_e,
    const float* __restrict__ b1, const float* __restrict__ W2,
    const float* __restrict__ as2w, const float* __restrict__ ad2w,
    const float* __restrict__ b2,
    const float* __restrict__ fc1_w, const float* __restrict__ fc1_b,
    const float* __restrict__ fc2_w, const float* __restrict__ fc2_b,
    float* __restrict__ out) {
    __shared__ float sh[2688];
    int tid = threadIdx.x, bid = blockIdx.x;
    int lane = tid & 31, warp = tid >> 5;

    // ===== phase A: proj1 (0..374) | CSR+ex+exs (375..562) | fill (375..739) ========
    if (bid < 375) {
        int i0 = bid * 4;
        for (int idx = tid; idx < 4 * IND; idx += NTHR)
            sh[idx] = x[i0 * IND + idx];
        __syncthreads();
        int j = tid & 127, half = tid >> 7;
        const float* xr = sh + (half * 2) * IND;
        float a0 = 0.f, a1 = 0.f;
        #pragma unroll 8
        for (int k = 0; k < IND; k++) {
            float w = W1[k * HC + j];
            a0 = fmaf(xr[k],       w, a0);
            a1 = fmaf(xr[IND + k], w, a1);
        }
        int h = j >> 5;
        float asw = as1[h * OUTC + lane], adw = ad1[h * OUTC + lane];
        float accs[2] = {a0, a1};
        #pragma unroll
        for (int r = 0; r < 2; r++) {
            int row = i0 + half * 2 + r;
            g_h[row * HC + j] = accs[r];
            float s = accs[r] * asw, d = accs[r] * adw;
            #pragma unroll
            for (int off = 16; off > 0; off >>= 1) {
                s += __shfl_down_sync(0xffffffffu, s, off);
                d += __shfl_down_sync(0xffffffffu, d, off);
            }
            if (lane == 0) {
                g_as[row * HEADS + h] = s;
                g_ad[row * HEADS + h] = d;
            }
        }
    } else {
        if (tid < EDIM * HEADS) {     // weatt -> sh[0..63]
            int d = tid >> 2, h = tid & 3;
            float acc = 0.f;
            #pragma unroll
            for (int c = 0; c < OUTC; c++)
                acc = fmaf(We[d * HC + h * OUTC + c], att_e[h * OUTC + c], acc);
            sh[tid] = acc;
        }
        __syncthreads();
        int t = (bid - 375) * NTHR + tid;   // CSR blocks 375..562 cover NE
        if (t < NE) {
            int src = edges[t];
            int dst = edges[NE + t];
            int slot = atomicAdd(&((int*)(g_z + OFF_DEG))[dst], 1);
            g_ebuf[dst * CAP + slot] = (t << 11) | src;
            float4 e0 = reinterpret_cast<const float4*>(ef + t * EDIM)[0];
            float4 e1 = reinterpret_cast<const float4*>(ef + t * EDIM)[1];
            float4 e2 = reinterpret_cast<const float4*>(ef + t * EDIM)[2];
            float4 e3 = reinterpret_cast<const float4*>(ef + t * EDIM)[3];
            float efv[16] = {e0.x,e0.y,e0.z,e0.w, e1.x,e1.y,e1.z,e1.w,
                             e2.x,e2.y,e2.z,e2.w, e3.x,e3.y,e3.z,e3.w};
            float4 exo;
            float* exp_ = &exo.x;
            #pragma unroll
            for (int h = 0; h < HEADS; h++) {
                float acc = 0.f;
                #pragma unroll
                for (int d = 0; d < EDIM; d++)
                    acc = fmaf(efv[d], sh[d * HEADS + h], acc);
                exp_[h] = acc;
            }
            reinterpret_cast<float4*>(g_ex)[t] = exo;
            atomicAdd(reinterpret_cast<float4*>(g_z + OFF_EXS + dst * HEADS), exo);
        }
        // constant fill of out rows >= NE
        float z0 = fc2_b[0], z1 = fc2_b[1];
        #pragma unroll
        for (int c = 0; c < 32; c++) {
            float hc = fmaxf(fc1_b[c], 0.f);
            z0 = fmaf(hc, fc2_w[c * 2 + 0], z0);
            z1 = fmaf(hc, fc2_w[c * 2 + 1], z1);
        }
        float mm = fmaxf(z0, z1);
        float e0 = __expf(z0 - mm), e1 = __expf(z1 - mm);
        float inv = __fdividef(1.f, e0 + e1);
        float4 v = make_float4(e0 * inv, e1 * inv, e0 * inv, e1 * inv);
        for (int idx = FILL_BASE + (bid - 375) * NTHR + tid; idx < FILL_TOTAL;
             idx += 365 * NTHR)
            reinterpret_cast<float4*>(out)[idx] = v;
    }

    gbar(1);

    // ===== phase B: gather layer 1 -> agg1, s1 (one task per warp, no atomics) ======
    gather_pass<true>(g_h, g_as, g_ad, g_agg1, g_s1, bid * 8 + warp, lane);

    gbar(2);

    // ===== phase C: proj2 (x1 combined+normalized on the fly) ========================
    if (bid < 375) {
        int i0 = bid * 4;
        if (tid < 128) {
            int row = i0 + (tid >> 5), c = tid & 31;
            sh[tid] = xval(g_agg1, g_s1, row, c, b1[c]);
        }
        __syncthreads();
        int j = tid & 127, half = tid >> 7;
        const float* xr = sh + (half * 2) * OUTC;
        float a0 = 0.f, a1 = 0.f;
        #pragma unroll
        for (int k = 0; k < OUTC; k++) {
            float w = W2[k * HC + j];
            a0 = fmaf(xr[k],        w, a0);
            a1 = fmaf(xr[OUTC + k], w, a1);
        }
        int h = j >> 5;
        float asw = as2w[h * OUTC + lane], adw = ad2w[h * OUTC + lane];
        float accs[2] = {a0, a1};
        #pragma unroll
        for (int r = 0; r < 2; r++) {
            int row = i0 + half * 2 + r;
            g_h2[row * HC + j] = accs[r];
            float s = accs[r] * asw, d = accs[r] * adw;
            #pragma unroll
            for (int off = 16; off > 0; off >>= 1) {
                s += __shfl_down_sync(0xffffffffu, s, off);
                d += __shfl_down_sync(0xffffffffu, d, off);
            }
            if (lane == 0) {
                g_as2[row * HEADS + h] = s;
                g_ad2[row * HEADS + h] = d;
            }
        }
        __syncthreads();
    }

    // preload classifier weights (independent of phase D)
    for (int i = tid; i < 2048; i += NTHR) sh[SH_W1 + i] = fc1_w[i];
    if (tid < 32) sh[SH_B1 + tid] = fc1_b[tid];
    if (tid < 64) sh[SH_W2 + tid] = fc2_w[tid];
    if (tid < 2)  sh[SH_B2 + tid] = fc2_b[tid];

    gbar(3);

    // ===== phase D: gather layer 2 -> agg2, s2 =======================================
    gather_pass<false>(g_h2, g_as2, g_ad2, g_agg2, g_s2, bid * 8 + warp, lane);

    gbar(4);

    // ===== phase E-pre: per-node classifier halves (x2 combined on the fly) ==========
    {
        int n = bid * 8 + warp;            // warp per node
        if (n < NN) {
            float xv = xval(g_agg2, g_s2, n, lane, b2[lane]);
            float yt = 0.f, yb = 0.f;
            #pragma unroll
            for (int k = 0; k < 32; k++) {
                float xk = __shfl_sync(0xffffffffu, xv, k);
                yt = fmaf(xk, sh[SH_W1 + k * 32 + lane],        yt);
                yb = fmaf(xk, sh[SH_W1 + (32 + k) * 32 + lane], yb);
            }
            g_y[n * 64 + lane]      = yt;
            g_y[n * 64 + 32 + lane] = yb;
        }
    }

    gbar(5);

    // ===== phase E: classifier (factorized; unroll-2 for MLP) ========================
    {
        float b1l = sh[SH_B1 + lane];
        float w20 = sh[SH_W2 + lane * 2 + 0];
        float w21 = sh[SH_W2 + lane * 2 + 1];
        float bz0 = sh[SH_B2], bz1 = sh[SH_B2 + 1];
        #pragma unroll 2
        for (int e = bid * 8 + warp; e < NE; e += NWARP) {
            int s0 = edges[e], d0 = edges[NE + e];
            float yt = g_y[s0 * 64 + lane];
            float yb = g_y[d0 * 64 + 32 + lane];
            float acc = fmaxf(yt + yb + b1l, 0.f);
            float z0 = acc * w20;
            float z1 = acc * w21;
            #pragma unroll
            for (int off = 16; off > 0; off >>= 1) {
                z0 += __shfl_down_sync(0xffffffffu, z0, off);
                z1 += __shfl_down_sync(0xffffffffu, z1, off);
            }
            if (lane == 0) {
                z0 += bz0; z1 += bz1;
                float mm = fmaxf(z0, z1);
                float e0 = __expf(z0 - mm), e1 = __expf(z1 - mm);
                float inv = __fdividef(1.f, e0 + e1);
                out[2 * e]     = e0 * inv;
                out[2 * e + 1] = e1 * inv;
            }
        }
    }
}

// ---- launch --------------------------------------------------------------------------
extern "C" void kernel_launch(void* const* d_in, const int* in_sizes, int n_in,
                              void* d_out, int out_size) {
    const float* x        = (const float*)d_in[0];
    const int*   edges    = (const int*)d_in[1];
    const float* ef       = (const float*)d_in[2];
    const float* W1       = (const float*)d_in[3];
    const float* att_src1 = (const float*)d_in[4];
    const float* att_dst1 = (const float*)d_in[5];
    const float* We       = (const float*)d_in[6];
    const float* att_e    = (const float*)d_in[7];
    const float* b1       = (const float*)d_in[8];
    const float* W2       = (const float*)d_in[9];
    const float* att_src2 = (const float*)d_in[10];
    const float* att_dst2 = (const float*)d_in[11];
    const float* b2       = (const float*)d_in[12];
    const float* fc1_w    = (const float*)d_in[13];
    const float* fc1_b    = (const float*)d_in[14];
    const float* fc2_w    = (const float*)d_in[15];
    const float* fc2_b    = (const float*)d_in[16];
    float* out = (float*)d_out;

    float* zbase; cudaGetSymbolAddress((void**)&zbase, g_z);
    cudaMemsetAsync(zbase, 0, ZTOTAL * sizeof(float));

    k_fused<<<NBLK, NTHR>>>(edges, ef, x, W1, att_src1, att_dst1, We, att_e,
                            b1, W2, att_src2, att_dst2, b2,
                            fc1_w, fc1_b, fc2_w, fc2_b, out);
}

// round 15
// speedup vs baseline: 1.0819x; 1.0819x over previous
#include <cuda_runtime.h>
#include <math.h>

#define NN    1500
#define NE    48000
#define IND   128
#define OUTC  32
#define HEADS 4
#define HC    128
#define EDIM  16
#define CAP   128

#define NBLK  740            // 148 SMs * 5 blocks
#define NTHR  256
#define NWARP (NBLK * 8)     // 5920
#define NTASK (NN * 4)       // (dst, head-pair, parity) = 6000

// ---- zeroed scratch (single memset) -------------------------------------------
#define OFF_DEG   0          // 1500 ints (CSR degree)
#define OFF_EXS   1504       // 6000: per-(dst,head) sum of edge extras
#define OFF_S1    7504       // 6000: layer-1 softmax denominators
#define OFF_S2    13504      // 6000
#define OFF_AGG1  19504      // 192000: raw per-head aggregation
#define OFF_AGG2  211504     // 192000
#define OFF_BAR   403504     // 2 ints (count, sense)
#define ZTOTAL    403508
__device__ __align__(16) float g_z[ZTOTAL];

// ---- non-zeroed scratch ----------------------------------------------------------
__device__ int   g_ebuf[NN * CAP];                 // packed (eid<<11)|src
__device__ __align__(16) float g_ex[NE * HEADS];   // per-edge attn extras
__device__ __align__(16) float g_h[NN * HC];
__device__ __align__(16) float g_as[NN * HEADS];
__device__ __align__(16) float g_ad[NN * HEADS];
__device__ __align__(16) float g_h2[NN * HC];
__device__ __align__(16) float g_as2[NN * HEADS];
__device__ __align__(16) float g_ad2[NN * HEADS];
__device__ __align__(16) float g_y[NN * 64];       // y_top | y_bot per node

#define FILL_BASE  (NE * 2 / 4)          // 24000 float4
#define FILL_TOTAL (NN * NN * 2 / 4)     // 1125000 float4

// ---- grid barrier without CCTL.IVALL (R9/R12 proven) --------------------------------
__device__ __forceinline__ void gbar(int phase) {
    __syncthreads();
    if (threadIdx.x == 0) {
        int* cnt = (int*)(g_z + OFF_BAR);
        int* sen = (int*)(g_z + OFF_BAR + 1);
        int prev;
        asm volatile("atom.acq_rel.gpu.add.s32 %0, [%1], 1;"
                     : "=r"(prev) : "l"(cnt) : "memory");
        if (prev == NBLK - 1) {
            *cnt = 0;
            asm volatile("st.release.gpu.s32 [%0], %1;"
                         :: "l"(sen), "r"(phase) : "memory");
        } else {
            int v;
            do {
                asm volatile("ld.acquire.gpu.s32 %0, [%1];"
                             : "=r"(v) : "l"(sen) : "memory");
            } while (v < phase);
        }
    }
    __syncthreads();
}

// ---- gather: task = (dst, head-pair, parity); raw (agg, s) emission -----------------
template <bool HAS_EXTRA>
__device__ __forceinline__ void gather_pass(const float* __restrict__ hb,
                                            const float* __restrict__ asb,
                                            const float* __restrict__ adb,
                                            float* __restrict__ agg,
                                            float* __restrict__ sbuf,
                                            int task, int lane) {
    if (task >= NTASK) return;
    int dst = task >> 2;
    int par = task & 1;
    int h   = (((task >> 1) & 1) << 1) + (lane >> 4);
    int l16 = lane & 15;
    int deg = ((const int*)(g_z + OFF_DEG))[dst];
    float ad_d = adb[dst * HEADS + h];
    const int* eb = g_ebuf + dst * CAP;

    float s = 0.f, ax = 0.f, ay = 0.f;
    int k = par;
    #pragma unroll 1
    for (; k + 6 < deg; k += 8) {
        int p[4]; float ex[4], asv[4]; float2 hv[4];
        #pragma unroll
        for (int u = 0; u < 4; u++) p[u] = eb[k + 2 * u];
        #pragma unroll
        for (int u = 0; u < 4; u++) {
            int src = p[u] & 2047;
            ex[u]  = HAS_EXTRA ? g_ex[(p[u] >> 11) * HEADS + h] : 0.f;
            asv[u] = asb[src * HEADS + h];
            hv[u]  = *reinterpret_cast<const float2*>(hb + src * HC + h * OUTC + l16 * 2);
        }
        #pragma unroll
        for (int u = 0; u < 4; u++) {
            float a = asv[u] + ad_d + ex[u];
            a = (a > 0.f) ? a : 0.2f * a;
            float e = __expf(a);
            s += e;
            ax = fmaf(e, hv[u].x, ax);
            ay = fmaf(e, hv[u].y, ay);
        }
    }
    for (; k < deg; k += 2) {
        int p = eb[k];
        int src = p & 2047;
        float ex = HAS_EXTRA ? g_ex[(p >> 11) * HEADS + h] : 0.f;
        float a = asb[src * HEADS + h] + ad_d + ex;
        a = (a > 0.f) ? a : 0.2f * a;
        float e = __expf(a);
        s += e;
        float2 hv = *reinterpret_cast<const float2*>(hb + src * HC + h * OUTC + l16 * 2);
        ax = fmaf(e, hv.x, ax);
        ay = fmaf(e, hv.y, ay);
    }
    if (par == 0) {   // self loop: attr = mean of incoming extras (0 if deg==0)
        float ex_sl = HAS_EXTRA
            ? __fdividef(g_z[OFF_EXS + dst * HEADS + h], fmaxf((float)deg, 1.f)) : 0.f;
        float a = asb[dst * HEADS + h] + ad_d + ex_sl;
        a = (a > 0.f) ? a : 0.2f * a;
        float e = __expf(a);
        s += e;
        float2 hv = *reinterpret_cast<const float2*>(hb + dst * HC + h * OUTC + l16 * 2);
        ax = fmaf(e, hv.x, ax);
        ay = fmaf(e, hv.y, ay);
    }
    atomicAdd(reinterpret_cast<float2*>(agg + dst * HC + h * OUTC + l16 * 2),
              make_float2(ax, ay));
    if (l16 == 0) atomicAdd(&sbuf[dst * HEADS + h], s);
}

// smem: [0..511] proj1 staging / weatt; [512..2559] fc1_w; [2560..2591] fc1_b;
//       [2592..2655] fc2_w; [2656..2657] fc2_b
#define SH_W1 512
#define SH_B1 2560
#define SH_W2 2592
#define SH_B2 2656

// ================= the single persistent kernel ======================================
__global__ void __launch_bounds__(NTHR, 5) k_fused(
    const int* __restrict__ edges, const float* __restrict__ ef,
    const float* __restrict__ x, const float* __restrict__ W1,
    const float* __restrict__ as1, const float* __restrict__ ad1,
    const float* __restrict__ We, const float* __restrict__ att_e,
    const float* __restrict__ b1, const float* __restrict__ W2,
    const float* __restrict__ as2w, const float* __restrict__ ad2w,
    const float* __restrict__ b2,
    const float* __restrict__ fc1_w, const float* __restrict__ fc1_b,
    const float* __restrict__ fc2_w, const float* __restrict__ fc2_b,
    float* __restrict__ out) {
    __shared__ float sh[2688];
    int tid = threadIdx.x, bid = blockIdx.x;
    int lane = tid & 31, warp = tid >> 5;

    // ===== phase A: proj1 (0..374) | CSR+ex+exs (375..562) ===========================
    if (bid < 375) {
        int i0 = bid * 4;
        for (int idx = tid; idx < 4 * IND; idx += NTHR)
            sh[idx] = x[i0 * IND + idx];
        __syncthreads();
        int j = tid & 127, half = tid >> 7;
        const float* xr = sh + (half * 2) * IND;
        float a0 = 0.f, a1 = 0.f;
        #pragma unroll 8
        for (int k = 0; k < IND; k++) {
            float w = W1[k * HC + j];
            a0 = fmaf(xr[k],       w, a0);
            a1 = fmaf(xr[IND + k], w, a1);
        }
        int h = j >> 5;
        float asw = as1[h * OUTC + lane], adw = ad1[h * OUTC + lane];
        float accs[2] = {a0, a1};
        #pragma unroll
        for (int r = 0; r < 2; r++) {
            int row = i0 + half * 2 + r;
            g_h[row * HC + j] = accs[r];
            float s = accs[r] * asw, d = accs[r] * adw;
            #pragma unroll
            for (int off = 16; off > 0; off >>= 1) {
                s += __shfl_down_sync(0xffffffffu, s, off);
                d += __shfl_down_sync(0xffffffffu, d, off);
            }
            if (lane == 0) {
                g_as[row * HEADS + h] = s;
                g_ad[row * HEADS + h] = d;
            }
        }
    } else {
        if (tid < EDIM * HEADS) {     // weatt -> sh[0..63]
            int d = tid >> 2, h = tid & 3;
            float acc = 0.f;
            #pragma unroll
            for (int c = 0; c < OUTC; c++)
                acc = fmaf(We[d * HC + h * OUTC + c], att_e[h * OUTC + c], acc);
            sh[tid] = acc;
        }
        __syncthreads();
        int t = (bid - 375) * NTHR + tid;   // CSR blocks 375..562 cover NE
        if (t < NE) {
            int src = edges[t];
            int dst = edges[NE + t];
            int slot = atomicAdd(&((int*)(g_z + OFF_DEG))[dst], 1);
            g_ebuf[dst * CAP + slot] = (t << 11) | src;
            float4 e0 = reinterpret_cast<const float4*>(ef + t * EDIM)[0];
            float4 e1 = reinterpret_cast<const float4*>(ef + t * EDIM)[1];
            float4 e2 = reinterpret_cast<const float4*>(ef + t * EDIM)[2];
            float4 e3 = reinterpret_cast<const float4*>(ef + t * EDIM)[3];
            float efv[16] = {e0.x,e0.y,e0.z,e0.w, e1.x,e1.y,e1.z,e1.w,
                             e2.x,e2.y,e2.z,e2.w, e3.x,e3.y,e3.z,e3.w};
            float4 exo;
            float* exp_ = &exo.x;
            #pragma unroll
            for (int h = 0; h < HEADS; h++) {
                float acc = 0.f;
                #pragma unroll
                for (int d = 0; d < EDIM; d++)
                    acc = fmaf(efv[d], sh[d * HEADS + h], acc);
                exp_[h] = acc;
            }
            reinterpret_cast<float4*>(g_ex)[t] = exo;
            atomicAdd(reinterpret_cast<float4*>(g_z + OFF_EXS + dst * HEADS), exo);
        }
    }

    gbar(1);

    // ===== phase B: gather layer 1 -> agg1, s1 =======================================
    for (int t = bid * 8 + warp; t < NTASK; t += NWARP)
        gather_pass<true>(g_h, g_as, g_ad, g_z + OFF_AGG1, g_z + OFF_S1, t, lane);

    gbar(2);

    // ===== phase C: proj2 (x1 normalized on the fly from agg1/s1) ====================
    if (bid < 375) {
        int i0 = bid * 4;
        if (tid < 128) {
            int row = i0 + (tid >> 5), c = tid & 31;
            const float* ag = g_z + OFF_AGG1 + row * HC;
            float4 sv = *reinterpret_cast<const float4*>(g_z + OFF_S1 + row * HEADS);
            sh[tid] = 0.25f * (__fdividef(ag[c],      sv.x) +
                               __fdividef(ag[32 + c], sv.y) +
                               __fdividef(ag[64 + c], sv.z) +
                               __fdividef(ag[96 + c], sv.w)) + b1[c];
        }
        __syncthreads();
        int j = tid & 127, half = tid >> 7;
        const float* xr = sh + (half * 2) * OUTC;
        float a0 = 0.f, a1 = 0.f;
        #pragma unroll
        for (int k = 0; k < OUTC; k++) {
            float w = W2[k * HC + j];
            a0 = fmaf(xr[k],        w, a0);
            a1 = fmaf(xr[OUTC + k], w, a1);
        }
        int h = j >> 5;
        float asw = as2w[h * OUTC + lane], adw = ad2w[h * OUTC + lane];
        float accs[2] = {a0, a1};
        #pragma unroll
        for (int r = 0; r < 2; r++) {
            int row = i0 + half * 2 + r;
            g_h2[row * HC + j] = accs[r];
            float s = accs[r] * asw, d = accs[r] * adw;
            #pragma unroll
            for (int off = 16; off > 0; off >>= 1) {
                s += __shfl_down_sync(0xffffffffu, s, off);
                d += __shfl_down_sync(0xffffffffu, d, off);
            }
            if (lane == 0) {
                g_as2[row * HEADS + h] = s;
                g_ad2[row * HEADS + h] = d;
            }
        }
        __syncthreads();
    }

    // preload classifier weights (independent of phase D)
    for (int i = tid; i < 2048; i += NTHR) sh[SH_W1 + i] = fc1_w[i];
    if (tid < 32) sh[SH_B1 + tid] = fc1_b[tid];
    if (tid < 64) sh[SH_W2 + tid] = fc2_w[tid];
    if (tid < 2)  sh[SH_B2 + tid] = fc2_b[tid];

    gbar(3);

    // ===== phase D: gather layer 2 -> agg2, s2 =======================================
    for (int t = bid * 8 + warp; t < NTASK; t += NWARP)
        gather_pass<false>(g_h2, g_as2, g_ad2, g_z + OFF_AGG2, g_z + OFF_S2, t, lane);

    gbar(4);

    // ===== phase E-pre: per-node classifier halves (x2 normalized on the fly) ========
    {
        int n = bid * 8 + warp;            // warp per node
        if (n < NN) {
            const float* ag = g_z + OFF_AGG2 + n * HC;
            float4 sv = *reinterpret_cast<const float4*>(g_z + OFF_S2 + n * HEADS);
            float xv = 0.25f * (__fdividef(ag[lane],      sv.x) +
                                __fdividef(ag[32 + lane], sv.y) +
                                __fdividef(ag[64 + lane], sv.z) +
                                __fdividef(ag[96 + lane], sv.w)) + b2[lane];
            float yt = 0.f, yb = 0.f;
            #pragma unroll
            for (int k = 0; k < 32; k++) {
                float xk = __shfl_sync(0xffffffffu, xv, k);
                yt = fmaf(xk, sh[SH_W1 + k * 32 + lane],        yt);
                yb = fmaf(xk, sh[SH_W1 + (32 + k) * 32 + lane], yb);
            }
            g_y[n * 64 + lane]      = yt;
            g_y[n * 64 + 32 + lane] = yb;
        }
    }

    gbar(5);

    // ===== phase E: constant fill (all blocks) + classifier ==========================
    {
        // fill rows >= NE with the constant softmax(relu(fc1_b)@fc2_w + fc2_b)
        float z0 = sh[SH_B2], z1 = sh[SH_B2 + 1];
        #pragma unroll
        for (int c = 0; c < 32; c++) {
            float hc = fmaxf(sh[SH_B1 + c], 0.f);
            z0 = fmaf(hc, sh[SH_W2 + c * 2 + 0], z0);
            z1 = fmaf(hc, sh[SH_W2 + c * 2 + 1], z1);
        }
        float mm = fmaxf(z0, z1);
        float fe0 = __expf(z0 - mm), fe1 = __expf(z1 - mm);
        float finv = __fdividef(1.f, fe0 + fe1);
        float4 v = make_float4(fe0 * finv, fe1 * finv, fe0 * finv, fe1 * finv);
        for (int idx = FILL_BASE + bid * NTHR + tid; idx < FILL_TOTAL; idx += NBLK * NTHR)
            reinterpret_cast<float4*>(out)[idx] = v;
    }
    {
        float b1l = sh[SH_B1 + lane];
        float w20 = sh[SH_W2 + lane * 2 + 0];
        float w21 = sh[SH_W2 + lane * 2 + 1];
        float bz0 = sh[SH_B2], bz1 = sh[SH_B2 + 1];
        for (int e = bid * 8 + warp; e < NE; e += NWARP) {
            int s0 = edges[e], d0 = edges[NE + e];
            float yt = g_y[s0 * 64 + lane];
            float yb = g_y[d0 * 64 + 32 + lane];
            float acc = fmaxf(yt + yb + b1l, 0.f);
            float z0 = acc * w20;
            float z1 = acc * w21;
            #pragma unroll
            for (int off = 16; off > 0; off >>= 1) {
                z0 += __shfl_down_sync(0xffffffffu, z0, off);
                z1 += __shfl_down_sync(0xffffffffu, z1, off);
            }
            if (lane == 0) {
                z0 += bz0; z1 += bz1;
                float mm = fmaxf(z0, z1);
                float e0 = __expf(z0 - mm), e1 = __expf(z1 - mm);
                float inv = __fdividef(1.f, e0 + e1);
                out[2 * e]     = e0 * inv;
                out[2 * e + 1] = e1 * inv;
            }
        }
    }
}

// ---- launch --------------------------------------------------------------------------
extern "C" void kernel_launch(void* const* d_in, const int* in_sizes, int n_in,
                              void* d_out, int out_size) {
    const float* x        = (const float*)d_in[0];
    const int*   edges    = (const int*)d_in[1];
    const float* ef       = (const float*)d_in[2];
    const float* W1       = (const float*)d_in[3];
    const float* att_src1 = (const float*)d_in[4];
    const float* att_dst1 = (const float*)d_in[5];
    const float* We       = (const float*)d_in[6];
    const float* att_e    = (const float*)d_in[7];
    const float* b1       = (const float*)d_in[8];
    const float* W2       = (const float*)d_in[9];
    const float* att_src2 = (const float*)d_in[10];
    const float* att_dst2 = (const float*)d_in[11];
    const float* b2       = (const float*)d_in[12];
    const float* fc1_w    = (const float*)d_in[13];
    const float* fc1_b    = (const float*)d_in[14];
    const float* fc2_w    = (const float*)d_in[15];
    const float* fc2_b    = (const float*)d_in[16];
    float* out = (float*)d_out;

    float* zbase; cudaGetSymbolAddress((void**)&zbase, g_z);
    cudaMemsetAsync(zbase, 0, ZTOTAL * sizeof(float));

    k_fused<<<NBLK, NTHR>>>(edges, ef, x, W1, att_src1, att_dst1, We, att_e,
                            b1, W2, att_src2, att_dst2, b2,
                            fc1_w, fc1_b, fc2_w, fc2_b, out);
}

// round 16
// speedup vs baseline: 1.2065x; 1.1152x over previous
#include <cuda_runtime.h>
#include <math.h>

#define NN    1500
#define NE    48000
#define IND   128
#define OUTC  32
#define HEADS 4
#define HC    128
#define EDIM  16
#define CAP   128

#define NBLK  740            // 148 SMs * 5 blocks
#define NTHR  256
#define NWARP (NBLK * 8)     // 5920
#define NTASK (NN * 4)       // (dst, head-pair, parity) = 6000

// ---- zeroed scratch (single memset) -------------------------------------------
#define OFF_DEG   0          // 1500 ints (CSR degree)
#define OFF_EXS   1504       // 6000: per-(dst,head) sum of edge extras
#define OFF_S1    7504       // 6000: layer-1 softmax denominators
#define OFF_S2    13504      // 6000
#define OFF_AGG1  19504      // 192000: raw per-head aggregation
#define OFF_AGG2  211504     // 192000
#define OFF_BAR   403504     // 2 ints (count, sense)
#define ZTOTAL    403508
__device__ __align__(16) float g_z[ZTOTAL];

// ---- non-zeroed scratch ----------------------------------------------------------
__device__ int   g_ebuf[NN * CAP];                 // packed (eid<<11)|src
__device__ __align__(16) float g_ex[NE * HEADS];   // per-edge attn extras
__device__ __align__(16) float g_h[NN * HC];
__device__ __align__(16) float g_as[NN * HEADS];
__device__ __align__(16) float g_ad[NN * HEADS];
__device__ __align__(16) float g_h2[NN * HC];
__device__ __align__(16) float g_as2[NN * HEADS];
__device__ __align__(16) float g_ad2[NN * HEADS];
__device__ __align__(16) float g_y[NN * 64];       // y_top | y_bot per node

#define FILL_BASE  (NE * 2 / 4)          // 24000 float4
#define FILL_TOTAL (NN * NN * 2 / 4)     // 1125000 float4

// ---- grid barrier without CCTL.IVALL (R12 proven; words zeroed by memset) ----------
__device__ __forceinline__ void gbar(int phase) {
    __syncthreads();
    if (threadIdx.x == 0) {
        int* cnt = (int*)(g_z + OFF_BAR);
        int* sen = (int*)(g_z + OFF_BAR + 1);
        int prev;
        asm volatile("atom.acq_rel.gpu.add.s32 %0, [%1], 1;"
                     : "=r"(prev) : "l"(cnt) : "memory");
        if (prev == NBLK - 1) {
            *cnt = 0;
            asm volatile("st.release.gpu.s32 [%0], %1;"
                         :: "l"(sen), "r"(phase) : "memory");
        } else {
            int v;
            do {
                asm volatile("ld.acquire.gpu.s32 %0, [%1];"
                             : "=r"(v) : "l"(sen) : "memory");
            } while (v < phase);
        }
    }
    __syncthreads();
}

// ---- gather: task = (dst, head-pair, parity); raw (agg, s) emission -----------------
template <bool HAS_EXTRA>
__device__ __forceinline__ void gather_pass(const float* __restrict__ hb,
                                            const float* __restrict__ asb,
                                            const float* __restrict__ adb,
                                            float* __restrict__ agg,
                                            float* __restrict__ sbuf,
                                            int task, int lane) {
    if (task >= NTASK) return;
    int dst = task >> 2;
    int par = task & 1;
    int h   = (((task >> 1) & 1) << 1) + (lane >> 4);
    int l16 = lane & 15;
    int deg = ((const int*)(g_z + OFF_DEG))[dst];
    float ad_d = adb[dst * HEADS + h];
    const int* eb = g_ebuf + dst * CAP;

    float s = 0.f, ax = 0.f, ay = 0.f;
    int k = par;
    #pragma unroll 1
    for (; k + 6 < deg; k += 8) {
        int p[4]; float ex[4], asv[4]; float2 hv[4];
        #pragma unroll
        for (int u = 0; u < 4; u++) p[u] = eb[k + 2 * u];
        #pragma unroll
        for (int u = 0; u < 4; u++) {
            int src = p[u] & 2047;
            ex[u]  = HAS_EXTRA ? g_ex[(p[u] >> 11) * HEADS + h] : 0.f;
            asv[u] = asb[src * HEADS + h];
            hv[u]  = *reinterpret_cast<const float2*>(hb + src * HC + h * OUTC + l16 * 2);
        }
        #pragma unroll
        for (int u = 0; u < 4; u++) {
            float a = asv[u] + ad_d + ex[u];
            a = (a > 0.f) ? a : 0.2f * a;
            float e = __expf(a);
            s += e;
            ax = fmaf(e, hv[u].x, ax);
            ay = fmaf(e, hv[u].y, ay);
        }
    }
    for (; k < deg; k += 2) {
        int p = eb[k];
        int src = p & 2047;
        float ex = HAS_EXTRA ? g_ex[(p >> 11) * HEADS + h] : 0.f;
        float a = asb[src * HEADS + h] + ad_d + ex;
        a = (a > 0.f) ? a : 0.2f * a;
        float e = __expf(a);
        s += e;
        float2 hv = *reinterpret_cast<const float2*>(hb + src * HC + h * OUTC + l16 * 2);
        ax = fmaf(e, hv.x, ax);
        ay = fmaf(e, hv.y, ay);
    }
    if (par == 0) {   // self loop: attr = mean of incoming extras (0 if deg==0)
        float ex_sl = HAS_EXTRA
            ? __fdividef(g_z[OFF_EXS + dst * HEADS + h], fmaxf((float)deg, 1.f)) : 0.f;
        float a = asb[dst * HEADS + h] + ad_d + ex_sl;
        a = (a > 0.f) ? a : 0.2f * a;
        float e = __expf(a);
        s += e;
        float2 hv = *reinterpret_cast<const float2*>(hb + dst * HC + h * OUTC + l16 * 2);
        ax = fmaf(e, hv.x, ax);
        ay = fmaf(e, hv.y, ay);
    }
    atomicAdd(reinterpret_cast<float2*>(agg + dst * HC + h * OUTC + l16 * 2),
              make_float2(ax, ay));
    if (l16 == 0) atomicAdd(&sbuf[dst * HEADS + h], s);
}

// x[node][lane] = mean over heads of agg/s + bias   (lane = channel)
__device__ __forceinline__ float xval(const float* __restrict__ agg,
                                      const float* __restrict__ sbuf,
                                      int n, int lane, float bias) {
    const float* ag = agg + n * HC;
    float4 sv = *reinterpret_cast<const float4*>(sbuf + n * HEADS);
    return 0.25f * (__fdividef(ag[lane],      sv.x) +
                    __fdividef(ag[32 + lane], sv.y) +
                    __fdividef(ag[64 + lane], sv.z) +
                    __fdividef(ag[96 + lane], sv.w)) + bias;
}

// smem: [0..511] proj1 staging / weatt; [512..2559] fc1_w; [2560..2591] fc1_b;
//       [2592..2655] fc2_w; [2656..2657] fc2_b
#define SH_W1 512
#define SH_B1 2560
#define SH_W2 2592
#define SH_B2 2656

// ================= the single persistent kernel ======================================
__global__ void __launch_bounds__(NTHR, 5) k_fused(
    const int* __restrict__ edges, const float* __restrict__ ef,
    const float* __restrict__ x, const float* __restrict__ W1,
    const float* __restrict__ as1, const float* __restrict__ ad1,
    const float* __restrict__ We, const float* __restrict__ att_e,
    const float* __restrict__ b1, const float* __restrict__ W2,
    const float* __restrict__ as2w, const float* __restrict__ ad2w,
    const float* __restrict__ b2,
    const float* __restrict__ fc1_w, const float* __restrict__ fc1_b,
    const float* __restrict__ fc2_w, const float* __restrict__ fc2_b,
    float* __restrict__ out) {
    __shared__ float sh[2688];
    int tid = threadIdx.x, bid = blockIdx.x;
    int lane = tid & 31, warp = tid >> 5;

    // ===== phase A: proj1 (0..374) | CSR+ex+exs (375..562) | fill (375..739) ========
    if (bid < 375) {
        int i0 = bid * 4;
        for (int idx = tid; idx < 4 * IND; idx += NTHR)
            sh[idx] = x[i0 * IND + idx];
        __syncthreads();
        int j = tid & 127, half = tid >> 7;
        const float* xr = sh + (half * 2) * IND;
        float a0 = 0.f, a1 = 0.f;
        #pragma unroll 8
        for (int k = 0; k < IND; k++) {
            float w = W1[k * HC + j];
            a0 = fmaf(xr[k],       w, a0);
            a1 = fmaf(xr[IND + k], w, a1);
        }
        int h = j >> 5;
        float asw = as1[h * OUTC + lane], adw = ad1[h * OUTC + lane];
        float accs[2] = {a0, a1};
        #pragma unroll
        for (int r = 0; r < 2; r++) {
            int row = i0 + half * 2 + r;
            g_h[row * HC + j] = accs[r];
            float s = accs[r] * asw, d = accs[r] * adw;
            #pragma unroll
            for (int off = 16; off > 0; off >>= 1) {
                s += __shfl_down_sync(0xffffffffu, s, off);
                d += __shfl_down_sync(0xffffffffu, d, off);
            }
            if (lane == 0) {
                g_as[row * HEADS + h] = s;
                g_ad[row * HEADS + h] = d;
            }
        }
    } else {
        if (tid < EDIM * HEADS) {     // weatt -> sh[0..63]
            int d = tid >> 2, h = tid & 3;
            float acc = 0.f;
            #pragma unroll
            for (int c = 0; c < OUTC; c++)
                acc = fmaf(We[d * HC + h * OUTC + c], att_e[h * OUTC + c], acc);
            sh[tid] = acc;
        }
        __syncthreads();
        int t = (bid - 375) * NTHR + tid;   // CSR blocks 375..562 cover NE
        if (t < NE) {
            int src = edges[t];
            int dst = edges[NE + t];
            int slot = atomicAdd(&((int*)(g_z + OFF_DEG))[dst], 1);
            g_ebuf[dst * CAP + slot] = (t << 11) | src;
            float4 e0 = reinterpret_cast<const float4*>(ef + t * EDIM)[0];
            float4 e1 = reinterpret_cast<const float4*>(ef + t * EDIM)[1];
            float4 e2 = reinterpret_cast<const float4*>(ef + t * EDIM)[2];
            float4 e3 = reinterpret_cast<const float4*>(ef + t * EDIM)[3];
            float efv[16] = {e0.x,e0.y,e0.z,e0.w, e1.x,e1.y,e1.z,e1.w,
                             e2.x,e2.y,e2.z,e2.w, e3.x,e3.y,e3.z,e3.w};
            float4 exo;
            float* exp_ = &exo.x;
            #pragma unroll
            for (int h = 0; h < HEADS; h++) {
                float acc = 0.f;
                #pragma unroll
                for (int d = 0; d < EDIM; d++)
                    acc = fmaf(efv[d], sh[d * HEADS + h], acc);
                exp_[h] = acc;
            }
            reinterpret_cast<float4*>(g_ex)[t] = exo;
            atomicAdd(reinterpret_cast<float4*>(g_z + OFF_EXS + dst * HEADS), exo);
        }
        // constant fill of out rows >= NE
        float z0 = fc2_b[0], z1 = fc2_b[1];
        #pragma unroll
        for (int c = 0; c < 32; c++) {
            float hc = fmaxf(fc1_b[c], 0.f);
            z0 = fmaf(hc, fc2_w[c * 2 + 0], z0);
            z1 = fmaf(hc, fc2_w[c * 2 + 1], z1);
        }
        float mm = fmaxf(z0, z1);
        float e0 = __expf(z0 - mm), e1 = __expf(z1 - mm);
        float inv = __fdividef(1.f, e0 + e1);
        float4 v = make_float4(e0 * inv, e1 * inv, e0 * inv, e1 * inv);
        for (int idx = FILL_BASE + (bid - 375) * NTHR + tid; idx < FILL_TOTAL;
             idx += 365 * NTHR)
            reinterpret_cast<float4*>(out)[idx] = v;
    }

    gbar(1);

    // ===== phase B+C fused: gather layer 1, then proj2 for this block's nodes =======
    for (int t = bid * 8 + warp; t < NTASK; t += NWARP)
        gather_pass<true>(g_h, g_as, g_ad, g_z + OFF_AGG1, g_z + OFF_S1, t, lane);

    __syncthreads();   // agg1/s1 for dsts {2b,2b+1} (+wrap) written by THIS block only

    // proj2: warp w -> node n0 + (w>>2), quarter q = w&3 (shuffle matvec)
    for (int n0 = bid * 2; n0 < NN; n0 += 1480) {
        int n = n0 + (warp >> 2);
        int q = warp & 3;
        float x1 = xval(g_z + OFF_AGG1, g_z + OFF_S1, n, lane, b1[lane]);
        float acc = 0.f;
        #pragma unroll
        for (int k = 0; k < 32; k++) {
            float xk = __shfl_sync(0xffffffffu, x1, k);
            acc = fmaf(xk, W2[k * HC + q * 32 + lane], acc);
        }
        g_h2[n * HC + q * 32 + lane] = acc;
        float s = acc * as2w[q * 32 + lane];
        float d = acc * ad2w[q * 32 + lane];
        #pragma unroll
        for (int off = 16; off > 0; off >>= 1) {
            s += __shfl_down_sync(0xffffffffu, s, off);
            d += __shfl_down_sync(0xffffffffu, d, off);
        }
        if (lane == 0) {
            g_as2[n * HEADS + q] = s;
            g_ad2[n * HEADS + q] = d;
        }
    }

    // preload classifier weights (consumed by E-pre and E, after gbar(2))
    for (int i = tid; i < 2048; i += NTHR) sh[SH_W1 + i] = fc1_w[i];
    if (tid < 32) sh[SH_B1 + tid] = fc1_b[tid];
    if (tid < 64) sh[SH_W2 + tid] = fc2_w[tid];
    if (tid < 2)  sh[SH_B2 + tid] = fc2_b[tid];

    gbar(2);

    // ===== phase D+E-pre fused: gather layer 2, then classifier halves ===============
    for (int t = bid * 8 + warp; t < NTASK; t += NWARP)
        gather_pass<false>(g_h2, g_as2, g_ad2, g_z + OFF_AGG2, g_z + OFF_S2, t, lane);

    __syncthreads();   // agg2/s2 for this block's nodes complete

    // E-pre: warps 0..3 -> node n0 + (w>>1), half hh = w&1
    for (int n0 = bid * 2; n0 < NN; n0 += 1480) {
        if (warp < 4) {
            int n = n0 + (warp >> 1);
            int hh = warp & 1;
            float xv = xval(g_z + OFF_AGG2, g_z + OFF_S2, n, lane, b2[lane]);
            float y = 0.f;
            #pragma unroll
            for (int k = 0; k < 32; k++) {
                float xk = __shfl_sync(0xffffffffu, xv, k);
                y = fmaf(xk, sh[SH_W1 + (hh * 32 + k) * 32 + lane], y);
            }
            g_y[n * 64 + hh * 32 + lane] = y;
        }
    }

    gbar(3);

    // ===== phase E: classifier (factorized) ==========================================
    {
        float b1l = sh[SH_B1 + lane];
        float w20 = sh[SH_W2 + lane * 2 + 0];
        float w21 = sh[SH_W2 + lane * 2 + 1];
        float bz0 = sh[SH_B2], bz1 = sh[SH_B2 + 1];
        for (int e = bid * 8 + warp; e < NE; e += NWARP) {
            int s0 = edges[e], d0 = edges[NE + e];
            float yt = g_y[s0 * 64 + lane];
            float yb = g_y[d0 * 64 + 32 + lane];
            float acc = fmaxf(yt + yb + b1l, 0.f);
            float z0 = acc * w20;
            float z1 = acc * w21;
            #pragma unroll
            for (int off = 16; off > 0; off >>= 1) {
                z0 += __shfl_down_sync(0xffffffffu, z0, off);
                z1 += __shfl_down_sync(0xffffffffu, z1, off);
            }
            if (lane == 0) {
                z0 += bz0; z1 += bz1;
                float mm = fmaxf(z0, z1);
                float e0 = __expf(z0 - mm), e1 = __expf(z1 - mm);
                float inv = __fdividef(1.f, e0 + e1);
                out[2 * e]     = e0 * inv;
                out[2 * e + 1] = e1 * inv;
            }
        }
    }
}

// ---- launch --------------------------------------------------------------------------
extern "C" void kernel_launch(void* const* d_in, const int* in_sizes, int n_in,
                              void* d_out, int out_size) {
    const float* x        = (const float*)d_in[0];
    const int*   edges    = (const int*)d_in[1];
    const float* ef       = (const float*)d_in[2];
    const float* W1       = (const float*)d_in[3];
    const float* att_src1 = (const float*)d_in[4];
    const float* att_dst1 = (const float*)d_in[5];
    const float* We       = (const float*)d_in[6];
    const float* att_e    = (const float*)d_in[7];
    const float* b1       = (const float*)d_in[8];
    const float* W2       = (const float*)d_in[9];
    const float* att_src2 = (const float*)d_in[10];
    const float* att_dst2 = (const float*)d_in[11];
    const float* b2       = (const float*)d_in[12];
    const float* fc1_w    = (const float*)d_in[13];
    const float* fc1_b    = (const float*)d_in[14];
    const float* fc2_w    = (const float*)d_in[15];
    const float* fc2_b    = (const float*)d_in[16];
    float* out = (float*)d_out;

    float* zbase; cudaGetSymbolAddress((void**)&zbase, g_z);
    cudaMemsetAsync(zbase, 0, ZTOTAL * sizeof(float));

    k_fused<<<NBLK, NTHR>>>(edges, ef, x, W1, att_src1, att_dst1, We, att_e,
                            b1, W2, att_src2, att_dst2, b2,
                            fc1_w, fc1_b, fc2_w, fc2_b, out);
}